// round 1
// baseline (speedup 1.0000x reference)
#include <cuda_runtime.h>

// ---------------------------------------------------------------------------
// JumpReLU SAE: two fused fp32 GEMMs using packed f32x2 FMA (sm_103a pipe).
//   GEMM1 (encode): features = JumpReLU((x - b_dec) @ W_enc + b_enc)
//   GEMM2 (decode): recon    = features @ W_dec + b_dec
// Output layout: d_out = [reconstruction (8192x2048) | features (8192x16384)]
// ---------------------------------------------------------------------------

#define BM 128
#define BN 128
#define BK 16
#define TM 8
#define TN 8
#define NT 256
#define APAD 4   // pad As rows to reduce smem store bank conflicts

// --- packed f32x2 helpers (Blackwell dual-fp32 pipe; only reachable via PTX) ---
__device__ __forceinline__ void fma2(unsigned long long& d,
                                     unsigned long long a,
                                     unsigned long long b) {
    asm("fma.rn.f32x2 %0, %1, %2, %0;" : "+l"(d) : "l"(a), "l"(b));
}
__device__ __forceinline__ unsigned long long pack2(float lo, float hi) {
    unsigned long long r;
    asm("mov.b64 %0, {%1, %2};" : "=l"(r) : "f"(lo), "f"(hi));
    return r;
}
__device__ __forceinline__ void unpack2(unsigned long long v, float& lo, float& hi) {
    asm("mov.b64 {%0, %1}, %2;" : "=f"(lo), "=f"(hi) : "l"(v));
}

// SUB:   subtract sub[k] from A elements while loading (b_dec on encode path)
// JRELU: apply (v > thr[col]) ? v : 0 in the epilogue (encode path)
template<bool SUB, bool JRELU>
__global__ __launch_bounds__(NT, 2)
void gemm_fused(int M, int N, int K,
                const float* __restrict__ A,
                const float* __restrict__ B,
                const float* __restrict__ bias,
                const float* __restrict__ thr,
                const float* __restrict__ sub,
                float* __restrict__ C)
{
    __shared__ float As[BK][BM + APAD];   // A tile stored transposed
    __shared__ float Bs[BK][BN];

    const int tid  = threadIdx.x;
    const int tCol = tid % (BN / TN);     // 0..15
    const int tRow = tid / (BN / TN);     // 0..15

    const float* Ag = A + (size_t)blockIdx.y * BM * K;
    const float* Bg = B + (size_t)blockIdx.x * BN;

    // global-load mapping (float4 loads, two passes each)
    const int aRow = tid / (BK / 4);          // 0..63
    const int aCol = (tid % (BK / 4)) * 4;    // 0,4,8,12
    const int bRow = tid / (BN / 4);          // 0..7
    const int bCol = (tid % (BN / 4)) * 4;    // 0..124

    float4 ra[2], rb[2];

    unsigned long long acc[TM][TN / 2];
    #pragma unroll
    for (int m = 0; m < TM; m++)
        #pragma unroll
        for (int n = 0; n < TN / 2; n++) acc[m][n] = 0ull;

    auto LOADG = [&](int k0) {
        #pragma unroll
        for (int i = 0; i < 2; i++)
            ra[i] = *reinterpret_cast<const float4*>(
                Ag + (size_t)(aRow + i * 64) * K + k0 + aCol);
        if (SUB) {
            float4 s = *reinterpret_cast<const float4*>(sub + k0 + aCol);
            #pragma unroll
            for (int i = 0; i < 2; i++) {
                ra[i].x -= s.x; ra[i].y -= s.y; ra[i].z -= s.z; ra[i].w -= s.w;
            }
        }
        #pragma unroll
        for (int i = 0; i < 2; i++)
            rb[i] = *reinterpret_cast<const float4*>(
                Bg + (size_t)(k0 + bRow + i * 8) * N + bCol);
    };

    auto STORES = [&]() {
        #pragma unroll
        for (int i = 0; i < 2; i++) {
            const int r = aRow + i * 64;
            As[aCol + 0][r] = ra[i].x;
            As[aCol + 1][r] = ra[i].y;
            As[aCol + 2][r] = ra[i].z;
            As[aCol + 3][r] = ra[i].w;
            *reinterpret_cast<float4*>(&Bs[bRow + i * 8][bCol]) = rb[i];
        }
    };

    LOADG(0);
    STORES();
    __syncthreads();

    for (int k0 = 0; k0 < K; k0 += BK) {
        const bool more = (k0 + BK) < K;
        if (more) LOADG(k0 + BK);   // prefetch next tile into registers

        #pragma unroll
        for (int k = 0; k < BK; k++) {
            // B fragment: natural packed pairs straight from shared (8B loads,
            // ptxas merges into LDS.128; conflict-free across the warp)
            unsigned long long b2[TN / 2];
            const float* bsrow = &Bs[k][tCol * TN];
            #pragma unroll
            for (int n = 0; n < TN / 2; n++)
                b2[n] = *reinterpret_cast<const unsigned long long*>(bsrow + 2 * n);

            const float* asrow = &As[k][tRow * TM];
            #pragma unroll
            for (int m = 0; m < TM; m++) {
                const float a = asrow[m];           // broadcast load
                const unsigned long long a2 = pack2(a, a);
                #pragma unroll
                for (int n = 0; n < TN / 2; n++)
                    fma2(acc[m][n], a2, b2[n]);     // 2 FMAs per instruction
            }
        }
        __syncthreads();
        if (more) { STORES(); __syncthreads(); }
    }

    // ---- fused epilogue ----
    const int gRowBase = blockIdx.y * BM + tRow * TM;
    const int gColBase = blockIdx.x * BN + tCol * TN;

    const float4 bi0 = *reinterpret_cast<const float4*>(bias + gColBase);
    const float4 bi1 = *reinterpret_cast<const float4*>(bias + gColBase + 4);
    float4 th0, th1;
    if (JRELU) {
        th0 = *reinterpret_cast<const float4*>(thr + gColBase);
        th1 = *reinterpret_cast<const float4*>(thr + gColBase + 4);
    }

    #pragma unroll
    for (int m = 0; m < TM; m++) {
        float o[TN];
        #pragma unroll
        for (int n = 0; n < TN / 2; n++) unpack2(acc[m][n], o[2 * n], o[2 * n + 1]);

        o[0] += bi0.x; o[1] += bi0.y; o[2] += bi0.z; o[3] += bi0.w;
        o[4] += bi1.x; o[5] += bi1.y; o[6] += bi1.z; o[7] += bi1.w;
        if (JRELU) {
            o[0] = (o[0] > th0.x) ? o[0] : 0.0f;
            o[1] = (o[1] > th0.y) ? o[1] : 0.0f;
            o[2] = (o[2] > th0.z) ? o[2] : 0.0f;
            o[3] = (o[3] > th0.w) ? o[3] : 0.0f;
            o[4] = (o[4] > th1.x) ? o[4] : 0.0f;
            o[5] = (o[5] > th1.y) ? o[5] : 0.0f;
            o[6] = (o[6] > th1.z) ? o[6] : 0.0f;
            o[7] = (o[7] > th1.w) ? o[7] : 0.0f;
        }

        float4* dst = reinterpret_cast<float4*>(
            C + (size_t)(gRowBase + m) * N + gColBase);
        dst[0] = make_float4(o[0], o[1], o[2], o[3]);
        dst[1] = make_float4(o[4], o[5], o[6], o[7]);
    }
}

extern "C" void kernel_launch(void* const* d_in, const int* in_sizes, int n_in,
                              void* d_out, int out_size) {
    const float* x     = (const float*)d_in[0];   // [8192, 2048]
    const float* W_enc = (const float*)d_in[1];   // [2048, 16384]
    const float* b_enc = (const float*)d_in[2];   // [16384]
    const float* thr   = (const float*)d_in[3];   // [16384]
    const float* W_dec = (const float*)d_in[4];   // [16384, 2048]
    const float* b_dec = (const float*)d_in[5];   // [2048]

    const int Nrows = 8192, D = 2048, S = 16384;

    float* recon = (float*)d_out;                       // [8192, 2048]
    float* feats = (float*)d_out + (size_t)Nrows * D;   // [8192, 16384]

    dim3 block(NT);

    // encode + JumpReLU -> features
    dim3 g1(S / BN, Nrows / BM);
    gemm_fused<true, true><<<g1, block>>>(Nrows, S, D,
                                          x, W_enc, b_enc, thr, b_dec, feats);

    // decode -> reconstruction
    dim3 g2(D / BN, Nrows / BM);
    gemm_fused<false, false><<<g2, block>>>(Nrows, D, S,
                                            feats, W_dec, b_dec, nullptr, nullptr,
                                            recon);
}

// round 5
// speedup vs baseline: 4.8142x; 4.8142x over previous
#include <cuda_runtime.h>
#include <cstdint>

// ===========================================================================
// JumpReLU SAE via mma.sync tf32 (target-portable tensor path; tcgen05 is
// rejected by this toolchain's compute_103 virtual arch).
//   prep:   W_encT = W_enc^T, W_decT = W_dec^T, bias_eff = b_enc - b_dec@W_enc
//   GEMM1:  feats = JumpReLU(x @ W_enc + bias_eff)     [8192 x 16384]
//   GEMM2:  recon = feats @ W_dec + b_dec              [8192 x 2048]
// GEMM form: C[M,N] = A[M,K] * B'[N,K]^T, A and B' both K-contiguous.
// ===========================================================================

#define BM 128
#define BN 256
#define BK 32
#define STAGES 3
#define NT 256            // 8 warps, 2 (M) x 4 (N), warp tile 64x64

#define ROWB 144                      // (BK+4)*4 bytes; 9 x 16B -> conflict-free ldmatrix
#define A_STAGE (BM * ROWB)           // 18432 B
#define B_STAGE (BN * ROWB)           // 36864 B
#define STAGE_BYTES (A_STAGE + B_STAGE)
#define SMEM_TOTAL (STAGES * STAGE_BYTES)   // 165888 B

// ------------------------- device scratch (no allocs allowed) --------------
__device__ __align__(16) float g_WencT[(size_t)16384 * 2048];   // [n][k]
__device__ __align__(16) float g_WdecT[(size_t)2048 * 16384];   // [n][k]
__device__ __align__(16) float g_biasEnc[16384];

// ------------------------------ PTX helpers --------------------------------
__device__ __forceinline__ uint32_t smem_u32(const void* p) {
    uint32_t a;
    asm("{ .reg .u64 t; cvta.to.shared.u64 t, %1; cvt.u32.u64 %0, t; }"
        : "=r"(a) : "l"(p));
    return a;
}
__device__ __forceinline__ void cp_async16(uint32_t dst, const void* src) {
    asm volatile("cp.async.cg.shared.global [%0], [%1], 16;"
                 :: "r"(dst), "l"(src) : "memory");
}
__device__ __forceinline__ void cp_commit() {
    asm volatile("cp.async.commit_group;" ::: "memory");
}
template <int N>
__device__ __forceinline__ void cp_wait_group() {
    asm volatile("cp.async.wait_group %0;" :: "n"(N) : "memory");
}
__device__ __forceinline__ void ldmatrix_x4(uint32_t* r, uint32_t addr) {
    asm volatile("ldmatrix.sync.aligned.m8n8.x4.shared.b16 {%0, %1, %2, %3}, [%4];"
                 : "=r"(r[0]), "=r"(r[1]), "=r"(r[2]), "=r"(r[3]) : "r"(addr));
}
__device__ __forceinline__ uint32_t to_tf32(uint32_t v) {
    uint32_t d;
    asm("cvt.rna.tf32.f32 %0, %1;" : "=r"(d) : "r"(v));
    return d;
}
__device__ __forceinline__ void mma_tf32(float* c, const uint32_t* a,
                                         const uint32_t* b) {
    asm volatile(
        "mma.sync.aligned.m16n8k8.row.col.f32.tf32.tf32.f32 "
        "{%0, %1, %2, %3}, {%4, %5, %6, %7}, {%8, %9}, {%0, %1, %2, %3};"
        : "+f"(c[0]), "+f"(c[1]), "+f"(c[2]), "+f"(c[3])
        : "r"(a[0]), "r"(a[1]), "r"(a[2]), "r"(a[3]), "r"(b[0]), "r"(b[1]));
}

// ------------------------------- prep kernels ------------------------------
// dst[C][R] = src[R][C]
__global__ void transpose_kernel(const float* __restrict__ src,
                                 float* __restrict__ dst, int R, int C) {
    __shared__ float tile[32][33];
    int x = blockIdx.x * 32 + threadIdx.x;
    int y = blockIdx.y * 32 + threadIdx.y;
    #pragma unroll
    for (int j = 0; j < 32; j += 8)
        tile[threadIdx.y + j][threadIdx.x] = src[(size_t)(y + j) * C + x];
    __syncthreads();
    x = blockIdx.y * 32 + threadIdx.x;
    y = blockIdx.x * 32 + threadIdx.y;
    #pragma unroll
    for (int j = 0; j < 32; j += 8)
        dst[(size_t)(y + j) * R + x] = tile[threadIdx.x][threadIdx.y + j];
}

// bias_eff[n] = b_enc[n] - sum_k b_dec[k] * W_enc[k][n]
__global__ void bias_corr_kernel(const float* __restrict__ W_enc,
                                 const float* __restrict__ b_dec,
                                 const float* __restrict__ b_enc,
                                 float* __restrict__ out, int K, int N) {
    int n = blockIdx.x * blockDim.x + threadIdx.x;
    float s = 0.f;
    for (int k = 0; k < K; k++)
        s += b_dec[k] * W_enc[(size_t)k * N + n];
    out[n] = b_enc[n] - s;
}

// ------------------------------- main GEMM ---------------------------------
template <bool JRELU>
__global__ __launch_bounds__(NT, 1)
void sae_gemm(const float* __restrict__ A,      // [M][K] K-contiguous
              const float* __restrict__ B,      // [Ntot][K] K-contiguous
              const float* __restrict__ bias,   // [Ntot]
              const float* __restrict__ thr,    // [Ntot] (JRELU only)
              float* __restrict__ C,            // [M][Ntot]
              int K, int Nout) {
    extern __shared__ __align__(16) char smem[];
    const uint32_t sb = smem_u32(smem);

    const int tid = threadIdx.x;
    const int wid = tid >> 5;
    const int l   = tid & 31;
    const int wm  = wid & 1;        // 0..1  (M direction)
    const int wn  = wid >> 1;       // 0..3  (N direction)

    const float* Ag = A + (size_t)blockIdx.y * BM * K;
    const float* Bg = B + (size_t)blockIdx.x * BN * K;

    const int n_iters = K / BK;

    // cp.async mapping: 16B chunks. A: 128 rows x 8 chunks; B: 256 rows x 8.
    const int ldRow = tid >> 3;          // 0..31
    const int ldChk = tid & 7;           // 0..7
    const size_t ldAsrc = (size_t)ldRow * K + ldChk * 4;
    const uint32_t ldAdst = (uint32_t)(ldRow * ROWB + ldChk * 16);

    auto issue_tile = [&](int t) {
        if (t < n_iters) {
            const uint32_t st = sb + (t % STAGES) * STAGE_BYTES;
            const int k0 = t * BK;
            const float* aS = Ag + k0;
            const float* bS = Bg + k0;
            #pragma unroll
            for (int i = 0; i < 4; i++)
                cp_async16(st + ldAdst + i * 32 * ROWB,
                           aS + ldAsrc + (size_t)i * 32 * K);
            #pragma unroll
            for (int i = 0; i < 8; i++)
                cp_async16(st + A_STAGE + ldAdst + i * 32 * ROWB,
                           bS + ldAsrc + (size_t)i * 32 * K);
        }
        cp_commit();   // uniform one group per slot (possibly empty)
    };

    // fragment smem byte-offsets (relative to stage base)
    uint32_t aoff[4], boff[4];
    #pragma unroll
    for (int i = 0; i < 4; i++)
        aoff[i] = (uint32_t)((wm * 64 + i * 16 + (l & 15)) * ROWB
                             + (l >> 4) * 16);
    #pragma unroll
    for (int j = 0; j < 4; j++)
        boff[j] = (uint32_t)(A_STAGE
                             + (wn * 64 + j * 16 + (l & 7) + ((l >> 4) << 3)) * ROWB
                             + ((l >> 3) & 1) * 16);

    float acc[4][8][4];
    #pragma unroll
    for (int i = 0; i < 4; i++)
        #pragma unroll
        for (int j = 0; j < 8; j++)
            #pragma unroll
            for (int q = 0; q < 4; q++) acc[i][j][q] = 0.f;

    issue_tile(0);
    issue_tile(1);

    for (int it = 0; it < n_iters; ++it) {
        cp_wait_group<1>();          // stage `it` resident
        __syncthreads();
        issue_tile(it + 2);          // safe: all warps past reads of this slot

        const uint32_t st = sb + (it % STAGES) * STAGE_BYTES;
        #pragma unroll
        for (int ks = 0; ks < BK / 8; ks++) {
            uint32_t af[4][4], bf[4][4];
            #pragma unroll
            for (int i = 0; i < 4; i++) {
                ldmatrix_x4(af[i], st + aoff[i] + ks * 32);
                #pragma unroll
                for (int q = 0; q < 4; q++) af[i][q] = to_tf32(af[i][q]);
            }
            #pragma unroll
            for (int j = 0; j < 4; j++) {
                ldmatrix_x4(bf[j], st + boff[j] + ks * 32);
                #pragma unroll
                for (int q = 0; q < 4; q++) bf[j][q] = to_tf32(bf[j][q]);
            }
            #pragma unroll
            for (int i = 0; i < 4; i++)
                #pragma unroll
                for (int j = 0; j < 4; j++) {
                    mma_tf32(acc[i][2 * j],     af[i], &bf[j][0]);
                    mma_tf32(acc[i][2 * j + 1], af[i], &bf[j][2]);
                }
        }
        __syncthreads();
    }

    // ---- fused epilogue ----
    const int cRow = blockIdx.y * BM + wm * 64;
    const int cCol = blockIdx.x * BN + wn * 64;

    #pragma unroll
    for (int i = 0; i < 4; i++) {
        const int r0 = cRow + i * 16 + (l >> 2);
        #pragma unroll
        for (int j = 0; j < 8; j++) {
            const int col = cCol + j * 8 + (l & 3) * 2;
            const float2 bv = *reinterpret_cast<const float2*>(bias + col);
            float v0 = acc[i][j][0] + bv.x;
            float v1 = acc[i][j][1] + bv.y;
            float v2 = acc[i][j][2] + bv.x;
            float v3 = acc[i][j][3] + bv.y;
            if (JRELU) {
                const float2 tv = *reinterpret_cast<const float2*>(thr + col);
                v0 = (v0 > tv.x) ? v0 : 0.f;
                v1 = (v1 > tv.y) ? v1 : 0.f;
                v2 = (v2 > tv.x) ? v2 : 0.f;
                v3 = (v3 > tv.y) ? v3 : 0.f;
            }
            *reinterpret_cast<float2*>(C + (size_t)r0 * Nout + col) =
                make_float2(v0, v1);
            *reinterpret_cast<float2*>(C + (size_t)(r0 + 8) * Nout + col) =
                make_float2(v2, v3);
        }
    }
}

// ------------------------------- launcher ----------------------------------
extern "C" void kernel_launch(void* const* d_in, const int* in_sizes, int n_in,
                              void* d_out, int out_size) {
    const float* x     = (const float*)d_in[0];   // [8192, 2048]
    const float* W_enc = (const float*)d_in[1];   // [2048, 16384]
    const float* b_enc = (const float*)d_in[2];   // [16384]
    const float* thr   = (const float*)d_in[3];   // [16384]
    const float* W_dec = (const float*)d_in[4];   // [16384, 2048]
    const float* b_dec = (const float*)d_in[5];   // [2048]

    const int Nrows = 8192, D = 2048, S = 16384;

    float* recon = (float*)d_out;                       // [8192, 2048]
    float* feats = (float*)d_out + (size_t)Nrows * D;   // [8192, 16384]

    float *wEncT, *wDecT, *biasEnc;
    cudaGetSymbolAddress((void**)&wEncT, g_WencT);
    cudaGetSymbolAddress((void**)&wDecT, g_WdecT);
    cudaGetSymbolAddress((void**)&biasEnc, g_biasEnc);

    cudaFuncSetAttribute(sae_gemm<true>,
                         cudaFuncAttributeMaxDynamicSharedMemorySize, SMEM_TOTAL);
    cudaFuncSetAttribute(sae_gemm<false>,
                         cudaFuncAttributeMaxDynamicSharedMemorySize, SMEM_TOTAL);

    // prep: transposed weights + effective encoder bias
    transpose_kernel<<<dim3(S / 32, D / 32), dim3(32, 8)>>>(W_enc, wEncT, D, S);
    transpose_kernel<<<dim3(D / 32, S / 32), dim3(32, 8)>>>(W_dec, wDecT, S, D);
    bias_corr_kernel<<<S / 256, 256>>>(W_enc, b_dec, b_enc, biasEnc, D, S);

    // encode: feats = JumpReLU(x @ W_enc + bias_eff)
    sae_gemm<true><<<dim3(S / BN, Nrows / BM), NT, SMEM_TOTAL>>>(
        x, wEncT, biasEnc, thr, feats, D, S);

    // decode: recon = feats @ W_dec + b_dec
    sae_gemm<false><<<dim3(D / BN, Nrows / BM), NT, SMEM_TOTAL>>>(
        feats, wDecT, b_dec, nullptr, recon, S, D);
}

// round 9
// speedup vs baseline: 5.2481x; 1.0901x over previous
#include <cuda_runtime.h>
#include <cstdint>

// ===========================================================================
// JumpReLU SAE via mma.sync tf32, 16-warp CTAs, cvt-free mainloop.
//   prep:   W_encT = round_tf32(W_enc^T), W_decT = round_tf32(W_dec^T)
//           xR = round_tf32(x), bias_eff = b_enc - b_dec@W_enc
//   GEMM1:  feats = JumpReLU(xR @ W_encT' + bias_eff)  -> d_out (exact)
//           + featsR = round_tf32(feats)               -> scratch
//   GEMM2:  recon = featsR @ W_decT' + b_dec
// GEMM form: C[M,N] = A[M,K] * B'[N,K]^T, operands pre-rounded to tf32.
// ===========================================================================

#define BM 128
#define BN 256
#define BK 32
#define STAGES 4
#define NT 512            // 16 warps: 2 (M) x 8 (N), warp tile 64x32

#define ROWB 144                      // (BK+4)*4 B; 9x16B rows -> conflict-free ldmatrix
#define A_STAGE (BM * ROWB)           // 18432 B
#define B_STAGE (BN * ROWB)           // 36864 B
#define STAGE_BYTES (A_STAGE + B_STAGE)          // 55296 B
#define SMEM_TOTAL (STAGES * STAGE_BYTES)        // 221184 B

// ------------------------- device scratch (no allocs allowed) --------------
__device__ __align__(16) float g_WencT[(size_t)16384 * 2048];   // [n][k] tf32
__device__ __align__(16) float g_WdecT[(size_t)2048 * 16384];   // [n][k] tf32
__device__ __align__(16) float g_xR[(size_t)8192 * 2048];       // x tf32
__device__ __align__(16) float g_featsR[(size_t)8192 * 16384];  // feats tf32
__device__ __align__(16) float g_biasEnc[16384];

// ------------------------------ PTX helpers --------------------------------
__device__ __forceinline__ uint32_t smem_u32(const void* p) {
    uint32_t a;
    asm("{ .reg .u64 t; cvta.to.shared.u64 t, %1; cvt.u32.u64 %0, t; }"
        : "=r"(a) : "l"(p));
    return a;
}
__device__ __forceinline__ void cp_async16(uint32_t dst, const void* src) {
    asm volatile("cp.async.cg.shared.global [%0], [%1], 16;"
                 :: "r"(dst), "l"(src) : "memory");
}
__device__ __forceinline__ void cp_commit() {
    asm volatile("cp.async.commit_group;" ::: "memory");
}
template <int N>
__device__ __forceinline__ void cp_wait_group() {
    asm volatile("cp.async.wait_group %0;" :: "n"(N) : "memory");
}
__device__ __forceinline__ void ldmatrix_x4(uint32_t* r, uint32_t addr) {
    asm volatile("ldmatrix.sync.aligned.m8n8.x4.shared.b16 {%0, %1, %2, %3}, [%4];"
                 : "=r"(r[0]), "=r"(r[1]), "=r"(r[2]), "=r"(r[3]) : "r"(addr));
}
__device__ __forceinline__ float round_tf32(float v) {
    float d;
    asm("cvt.rna.tf32.f32 %0, %1;" : "=f"(d) : "f"(v));
    return d;
}
__device__ __forceinline__ void mma_tf32(float* c, const uint32_t* a,
                                         const uint32_t* b) {
    asm volatile(
        "mma.sync.aligned.m16n8k8.row.col.f32.tf32.tf32.f32 "
        "{%0, %1, %2, %3}, {%4, %5, %6, %7}, {%8, %9}, {%0, %1, %2, %3};"
        : "+f"(c[0]), "+f"(c[1]), "+f"(c[2]), "+f"(c[3])
        : "r"(a[0]), "r"(a[1]), "r"(a[2]), "r"(a[3]), "r"(b[0]), "r"(b[1]));
}

// ------------------------------- prep kernels ------------------------------
// dst[C][R] = round_tf32(src[R][C])
__global__ void transpose_round_kernel(const float* __restrict__ src,
                                       float* __restrict__ dst, int R, int C) {
    __shared__ float tile[32][33];
    int x = blockIdx.x * 32 + threadIdx.x;
    int y = blockIdx.y * 32 + threadIdx.y;
    #pragma unroll
    for (int j = 0; j < 32; j += 8)
        tile[threadIdx.y + j][threadIdx.x] =
            round_tf32(src[(size_t)(y + j) * C + x]);
    __syncthreads();
    x = blockIdx.y * 32 + threadIdx.x;
    y = blockIdx.x * 32 + threadIdx.y;
    #pragma unroll
    for (int j = 0; j < 32; j += 8)
        dst[(size_t)(y + j) * R + x] = tile[threadIdx.x][threadIdx.y + j];
}

__global__ void round_kernel(const float* __restrict__ src,
                             float* __restrict__ dst, size_t n4) {
    size_t i = (size_t)blockIdx.x * blockDim.x + threadIdx.x;
    if (i < n4) {
        float4 v = reinterpret_cast<const float4*>(src)[i];
        v.x = round_tf32(v.x); v.y = round_tf32(v.y);
        v.z = round_tf32(v.z); v.w = round_tf32(v.w);
        reinterpret_cast<float4*>(dst)[i] = v;
    }
}

// bias_eff[n] = b_enc[n] - sum_k b_dec[k] * W_enc[k][n]
__global__ void bias_corr_kernel(const float* __restrict__ W_enc,
                                 const float* __restrict__ b_dec,
                                 const float* __restrict__ b_enc,
                                 float* __restrict__ out, int K, int N) {
    int n = blockIdx.x * blockDim.x + threadIdx.x;
    float s = 0.f;
    for (int k = 0; k < K; k++)
        s += b_dec[k] * W_enc[(size_t)k * N + n];
    out[n] = b_enc[n] - s;
}

// ------------------------------- main GEMM ---------------------------------
// ENC: JumpReLU epilogue + dual store (exact -> C, tf32-rounded -> Cr)
template <bool ENC>
__global__ __launch_bounds__(NT, 1)
void sae_gemm(const float* __restrict__ A,      // [M][K] K-contig, tf32 values
              const float* __restrict__ B,      // [Ntot][K] K-contig, tf32 values
              const float* __restrict__ bias,   // [Ntot]
              const float* __restrict__ thr,    // [Ntot] (ENC only)
              float* __restrict__ C,            // [M][Ntot]
              float* __restrict__ Cr,           // [M][Ntot] rounded copy (ENC)
              int K, int Nout) {
    extern __shared__ __align__(16) char smem[];
    const uint32_t sb = smem_u32(smem);

    const int tid = threadIdx.x;
    const int wid = tid >> 5;
    const int l   = tid & 31;
    const int wm  = wid & 1;        // 0..1 (M)
    const int wn  = wid >> 1;       // 0..7 (N)

    const float* Ag = A + (size_t)blockIdx.y * BM * K;
    const float* Bg = B + (size_t)blockIdx.x * BN * K;

    const int n_iters = K / BK;

    // cp.async mapping: 16B chunks, 512 threads.
    const int ldRow = tid >> 3;          // 0..63
    const int ldChk = tid & 7;           // 0..7
    const size_t ldSrc  = (size_t)ldRow * K + ldChk * 4;
    const uint32_t ldDst = (uint32_t)(ldRow * ROWB + ldChk * 16);

    auto issue_tile = [&](int t) {
        if (t < n_iters) {
            const uint32_t st = sb + (t & (STAGES - 1)) * STAGE_BYTES;
            const int k0 = t * BK;
            const float* aS = Ag + k0;
            const float* bS = Bg + k0;
            #pragma unroll
            for (int i = 0; i < 2; i++)      // A: 128 rows
                cp_async16(st + ldDst + i * 64 * ROWB,
                           aS + ldSrc + (size_t)i * 64 * K);
            #pragma unroll
            for (int i = 0; i < 4; i++)      // B: 256 rows
                cp_async16(st + A_STAGE + ldDst + i * 64 * ROWB,
                           bS + ldSrc + (size_t)i * 64 * K);
        }
        cp_commit();   // uniform one group per slot (possibly empty)
    };

    // fragment smem byte-offsets (relative to stage base)
    uint32_t aoff[4], boff[2];
    #pragma unroll
    for (int i = 0; i < 4; i++)
        aoff[i] = (uint32_t)((wm * 64 + i * 16 + (l & 15)) * ROWB
                             + (l >> 4) * 16);
    #pragma unroll
    for (int j = 0; j < 2; j++)
        boff[j] = (uint32_t)(A_STAGE
                             + (wn * 32 + j * 16 + (l & 7) + ((l >> 4) << 3)) * ROWB
                             + ((l >> 3) & 1) * 16);

    float acc[4][4][4];
    #pragma unroll
    for (int i = 0; i < 4; i++)
        #pragma unroll
        for (int j = 0; j < 4; j++)
            #pragma unroll
            for (int q = 0; q < 4; q++) acc[i][j][q] = 0.f;

    issue_tile(0);
    issue_tile(1);
    issue_tile(2);

    for (int it = 0; it < n_iters; ++it) {
        cp_wait_group<2>();          // tile `it` resident
        __syncthreads();             // all warps done with iter it-1
        issue_tile(it + 3);          // writes slot (it-1)%4: safe after barrier

        const uint32_t st = sb + (it & (STAGES - 1)) * STAGE_BYTES;
        #pragma unroll
        for (int ks = 0; ks < BK / 8; ks++) {
            uint32_t af[4][4], bf[2][4];
            #pragma unroll
            for (int i = 0; i < 4; i++)
                ldmatrix_x4(af[i], st + aoff[i] + ks * 32);
            #pragma unroll
            for (int j = 0; j < 2; j++)
                ldmatrix_x4(bf[j], st + boff[j] + ks * 32);
            #pragma unroll
            for (int i = 0; i < 4; i++) {
                mma_tf32(acc[i][0], af[i], &bf[0][0]);
                mma_tf32(acc[i][1], af[i], &bf[0][2]);
                mma_tf32(acc[i][2], af[i], &bf[1][0]);
                mma_tf32(acc[i][3], af[i], &bf[1][2]);
            }
        }
    }

    // ---- fused epilogue ----
    const int cRow = blockIdx.y * BM + wm * 64;
    const int cCol = blockIdx.x * BN + wn * 32;

    #pragma unroll
    for (int i = 0; i < 4; i++) {
        const int r0 = cRow + i * 16 + (l >> 2);
        #pragma unroll
        for (int j = 0; j < 4; j++) {
            const int col = cCol + j * 8 + (l & 3) * 2;
            const float2 bv = *reinterpret_cast<const float2*>(bias + col);
            float v0 = acc[i][j][0] + bv.x;
            float v1 = acc[i][j][1] + bv.y;
            float v2 = acc[i][j][2] + bv.x;
            float v3 = acc[i][j][3] + bv.y;
            if (ENC) {
                const float2 tv = *reinterpret_cast<const float2*>(thr + col);
                v0 = (v0 > tv.x) ? v0 : 0.f;
                v1 = (v1 > tv.y) ? v1 : 0.f;
                v2 = (v2 > tv.x) ? v2 : 0.f;
                v3 = (v3 > tv.y) ? v3 : 0.f;
            }
            const size_t o0 = (size_t)r0 * Nout + col;
            const size_t o1 = (size_t)(r0 + 8) * Nout + col;
            *reinterpret_cast<float2*>(C + o0) = make_float2(v0, v1);
            *reinterpret_cast<float2*>(C + o1) = make_float2(v2, v3);
            if (ENC) {
                *reinterpret_cast<float2*>(Cr + o0) =
                    make_float2(round_tf32(v0), round_tf32(v1));
                *reinterpret_cast<float2*>(Cr + o1) =
                    make_float2(round_tf32(v2), round_tf32(v3));
            }
        }
    }
}

// ------------------------------- launcher ----------------------------------
extern "C" void kernel_launch(void* const* d_in, const int* in_sizes, int n_in,
                              void* d_out, int out_size) {
    const float* x     = (const float*)d_in[0];   // [8192, 2048]
    const float* W_enc = (const float*)d_in[1];   // [2048, 16384]
    const float* b_enc = (const float*)d_in[2];   // [16384]
    const float* thr   = (const float*)d_in[3];   // [16384]
    const float* W_dec = (const float*)d_in[4];   // [16384, 2048]
    const float* b_dec = (const float*)d_in[5];   // [2048]

    const int Nrows = 8192, D = 2048, S = 16384;

    float* recon = (float*)d_out;                       // [8192, 2048]
    float* feats = (float*)d_out + (size_t)Nrows * D;   // [8192, 16384]

    float *wEncT, *wDecT, *xR, *featsR, *biasEnc;
    cudaGetSymbolAddress((void**)&wEncT, g_WencT);
    cudaGetSymbolAddress((void**)&wDecT, g_WdecT);
    cudaGetSymbolAddress((void**)&xR, g_xR);
    cudaGetSymbolAddress((void**)&featsR, g_featsR);
    cudaGetSymbolAddress((void**)&biasEnc, g_biasEnc);

    cudaFuncSetAttribute(sae_gemm<true>,
                         cudaFuncAttributeMaxDynamicSharedMemorySize, SMEM_TOTAL);
    cudaFuncSetAttribute(sae_gemm<false>,
                         cudaFuncAttributeMaxDynamicSharedMemorySize, SMEM_TOTAL);

    // prep: tf32-rounded transposed weights, rounded x, effective encoder bias
    transpose_round_kernel<<<dim3(S / 32, D / 32), dim3(32, 8)>>>(W_enc, wEncT, D, S);
    transpose_round_kernel<<<dim3(D / 32, S / 32), dim3(32, 8)>>>(W_dec, wDecT, S, D);
    {
        size_t n4 = (size_t)Nrows * D / 4;
        round_kernel<<<(unsigned)((n4 + 255) / 256), 256>>>(x, xR, n4);
    }
    bias_corr_kernel<<<S / 256, 256>>>(W_enc, b_dec, b_enc, biasEnc, D, S);

    // encode: feats = JumpReLU(xR @ W_enc + bias_eff); featsR = tf32(feats)
    sae_gemm<true><<<dim3(S / BN, Nrows / BM), NT, SMEM_TOTAL>>>(
        xR, wEncT, biasEnc, thr, feats, featsR, D, S);

    // decode: recon = featsR @ W_dec + b_dec
    sae_gemm<false><<<dim3(D / BN, Nrows / BM), NT, SMEM_TOTAL>>>(
        featsR, wDecT, b_dec, nullptr, recon, nullptr, S, D);
}

// round 10
// speedup vs baseline: 5.4609x; 1.0405x over previous
#include <cuda_runtime.h>
#include <cstdint>

// ===========================================================================
// JumpReLU SAE via mma.sync tf32, 16-warp CTAs, cvt-free mainloop.
//   prep:   W_encT = round_tf32(W_enc^T), W_decT = round_tf32(W_dec^T)
//           xR = round_tf32(x), bias_eff = b_enc - b_dec@W_enc (split-K)
//   GEMM1:  feats = round_tf32(JumpReLU(xR @ W_encT' + bias_eff)) -> d_out
//   GEMM2:  recon = feats @ W_decT' + b_dec   (reads feats from d_out)
// GEMM form: C[M,N] = A[M,K] * B'[N,K]^T, operands pre-rounded to tf32.
// Mainloop is at its smem-crossbar bound (~682 MAC/cyc/SM); this round
// removes launcher-side overhead (bias_corr 279us, featsR 536MB store).
// ===========================================================================

#define BM 128
#define BN 256
#define BK 32
#define STAGES 4
#define NT 512            // 16 warps: 2 (M) x 8 (N), warp tile 64x32

#define ROWB 144                      // (BK+4)*4 B; 9x16B rows -> conflict-free ldmatrix
#define A_STAGE (BM * ROWB)           // 18432 B
#define B_STAGE (BN * ROWB)           // 36864 B
#define STAGE_BYTES (A_STAGE + B_STAGE)          // 55296 B
#define SMEM_TOTAL (STAGES * STAGE_BYTES)        // 221184 B

#define BC_SPLIT 8        // split-K factor for bias correction

// ------------------------- device scratch (no allocs allowed) --------------
__device__ __align__(16) float g_WencT[(size_t)16384 * 2048];   // [n][k] tf32
__device__ __align__(16) float g_WdecT[(size_t)2048 * 16384];   // [n][k] tf32
__device__ __align__(16) float g_xR[(size_t)8192 * 2048];       // x tf32
__device__ __align__(16) float g_biasPart[BC_SPLIT * 16384];
__device__ __align__(16) float g_biasEnc[16384];

// ------------------------------ PTX helpers --------------------------------
__device__ __forceinline__ uint32_t smem_u32(const void* p) {
    uint32_t a;
    asm("{ .reg .u64 t; cvta.to.shared.u64 t, %1; cvt.u32.u64 %0, t; }"
        : "=r"(a) : "l"(p));
    return a;
}
__device__ __forceinline__ void cp_async16(uint32_t dst, const void* src) {
    asm volatile("cp.async.cg.shared.global [%0], [%1], 16;"
                 :: "r"(dst), "l"(src) : "memory");
}
__device__ __forceinline__ void cp_commit() {
    asm volatile("cp.async.commit_group;" ::: "memory");
}
template <int N>
__device__ __forceinline__ void cp_wait_group() {
    asm volatile("cp.async.wait_group %0;" :: "n"(N) : "memory");
}
__device__ __forceinline__ void ldmatrix_x4(uint32_t* r, uint32_t addr) {
    asm volatile("ldmatrix.sync.aligned.m8n8.x4.shared.b16 {%0, %1, %2, %3}, [%4];"
                 : "=r"(r[0]), "=r"(r[1]), "=r"(r[2]), "=r"(r[3]) : "r"(addr));
}
__device__ __forceinline__ float round_tf32(float v) {
    float d;
    asm("cvt.rna.tf32.f32 %0, %1;" : "=f"(d) : "f"(v));
    return d;
}
__device__ __forceinline__ void mma_tf32(float* c, const uint32_t* a,
                                         const uint32_t* b) {
    asm volatile(
        "mma.sync.aligned.m16n8k8.row.col.f32.tf32.tf32.f32 "
        "{%0, %1, %2, %3}, {%4, %5, %6, %7}, {%8, %9}, {%0, %1, %2, %3};"
        : "+f"(c[0]), "+f"(c[1]), "+f"(c[2]), "+f"(c[3])
        : "r"(a[0]), "r"(a[1]), "r"(a[2]), "r"(a[3]), "r"(b[0]), "r"(b[1]));
}

// ------------------------------- prep kernels ------------------------------
// dst[C][R] = round_tf32(src[R][C])
__global__ void transpose_round_kernel(const float* __restrict__ src,
                                       float* __restrict__ dst, int R, int C) {
    __shared__ float tile[32][33];
    int x = blockIdx.x * 32 + threadIdx.x;
    int y = blockIdx.y * 32 + threadIdx.y;
    #pragma unroll
    for (int j = 0; j < 32; j += 8)
        tile[threadIdx.y + j][threadIdx.x] =
            round_tf32(src[(size_t)(y + j) * C + x]);
    __syncthreads();
    x = blockIdx.y * 32 + threadIdx.x;
    y = blockIdx.x * 32 + threadIdx.y;
    #pragma unroll
    for (int j = 0; j < 32; j += 8)
        dst[(size_t)(y + j) * R + x] = tile[threadIdx.x][threadIdx.y + j];
}

__global__ void round_kernel(const float* __restrict__ src,
                             float* __restrict__ dst, size_t n4) {
    size_t i = (size_t)blockIdx.x * blockDim.x + threadIdx.x;
    if (i < n4) {
        float4 v = reinterpret_cast<const float4*>(src)[i];
        v.x = round_tf32(v.x); v.y = round_tf32(v.y);
        v.z = round_tf32(v.z); v.w = round_tf32(v.w);
        reinterpret_cast<float4*>(dst)[i] = v;
    }
}

// split-K partials: part[ky][n] = sum_{k in chunk ky} b_dec[k] * W_enc[k][n]
__global__ void bias_part_kernel(const float* __restrict__ W_enc,
                                 const float* __restrict__ b_dec,
                                 float* __restrict__ part, int K, int N) {
    const int n  = blockIdx.x * blockDim.x + threadIdx.x;
    const int ky = blockIdx.y;
    const int kc = K / BC_SPLIT;
    const int k0 = ky * kc;
    float s = 0.f;
    #pragma unroll 4
    for (int k = k0; k < k0 + kc; k++)
        s += b_dec[k] * W_enc[(size_t)k * N + n];
    part[(size_t)ky * N + n] = s;
}

// bias_eff[n] = b_enc[n] - sum_ky part[ky][n]   (deterministic reduce)
__global__ void bias_reduce_kernel(const float* __restrict__ part,
                                   const float* __restrict__ b_enc,
                                   float* __restrict__ out, int N) {
    const int n = blockIdx.x * blockDim.x + threadIdx.x;
    float s = 0.f;
    #pragma unroll
    for (int ky = 0; ky < BC_SPLIT; ky++)
        s += part[(size_t)ky * N + n];
    out[n] = b_enc[n] - s;
}

// ------------------------------- main GEMM ---------------------------------
// ENC: JumpReLU epilogue, output stored tf32-rounded (consumed by decode)
template <bool ENC>
__global__ __launch_bounds__(NT, 1)
void sae_gemm(const float* __restrict__ A,      // [M][K] K-contig, tf32 values
              const float* __restrict__ B,      // [Ntot][K] K-contig, tf32 values
              const float* __restrict__ bias,   // [Ntot]
              const float* __restrict__ thr,    // [Ntot] (ENC only)
              float* __restrict__ C,            // [M][Ntot]
              int K, int Nout) {
    extern __shared__ __align__(16) char smem[];
    const uint32_t sb = smem_u32(smem);

    const int tid = threadIdx.x;
    const int wid = tid >> 5;
    const int l   = tid & 31;
    const int wm  = wid & 1;        // 0..1 (M)
    const int wn  = wid >> 1;       // 0..7 (N)

    const float* Ag = A + (size_t)blockIdx.y * BM * K;
    const float* Bg = B + (size_t)blockIdx.x * BN * K;

    const int n_iters = K / BK;

    // cp.async mapping: 16B chunks, 512 threads.
    const int ldRow = tid >> 3;          // 0..63
    const int ldChk = tid & 7;           // 0..7
    const size_t ldSrc  = (size_t)ldRow * K + ldChk * 4;
    const uint32_t ldDst = (uint32_t)(ldRow * ROWB + ldChk * 16);

    auto issue_tile = [&](int t) {
        if (t < n_iters) {
            const uint32_t st = sb + (t & (STAGES - 1)) * STAGE_BYTES;
            const int k0 = t * BK;
            const float* aS = Ag + k0;
            const float* bS = Bg + k0;
            #pragma unroll
            for (int i = 0; i < 2; i++)      // A: 128 rows
                cp_async16(st + ldDst + i * 64 * ROWB,
                           aS + ldSrc + (size_t)i * 64 * K);
            #pragma unroll
            for (int i = 0; i < 4; i++)      // B: 256 rows
                cp_async16(st + A_STAGE + ldDst + i * 64 * ROWB,
                           bS + ldSrc + (size_t)i * 64 * K);
        }
        cp_commit();   // uniform one group per slot (possibly empty)
    };

    // fragment smem byte-offsets (relative to stage base)
    uint32_t aoff[4], boff[2];
    #pragma unroll
    for (int i = 0; i < 4; i++)
        aoff[i] = (uint32_t)((wm * 64 + i * 16 + (l & 15)) * ROWB
                             + (l >> 4) * 16);
    #pragma unroll
    for (int j = 0; j < 2; j++)
        boff[j] = (uint32_t)(A_STAGE
                             + (wn * 32 + j * 16 + (l & 7) + ((l >> 4) << 3)) * ROWB
                             + ((l >> 3) & 1) * 16);

    float acc[4][4][4];
    #pragma unroll
    for (int i = 0; i < 4; i++)
        #pragma unroll
        for (int j = 0; j < 4; j++)
            #pragma unroll
            for (int q = 0; q < 4; q++) acc[i][j][q] = 0.f;

    issue_tile(0);
    issue_tile(1);
    issue_tile(2);

    for (int it = 0; it < n_iters; ++it) {
        cp_wait_group<2>();          // tile `it` resident
        __syncthreads();             // all warps done with iter it-1
        issue_tile(it + 3);          // writes slot (it-1)%4: safe after barrier

        const uint32_t st = sb + (it & (STAGES - 1)) * STAGE_BYTES;
        #pragma unroll
        for (int ks = 0; ks < BK / 8; ks++) {
            uint32_t af[4][4], bf[2][4];
            #pragma unroll
            for (int i = 0; i < 4; i++)
                ldmatrix_x4(af[i], st + aoff[i] + ks * 32);
            #pragma unroll
            for (int j = 0; j < 2; j++)
                ldmatrix_x4(bf[j], st + boff[j] + ks * 32);
            #pragma unroll
            for (int i = 0; i < 4; i++) {
                mma_tf32(acc[i][0], af[i], &bf[0][0]);
                mma_tf32(acc[i][1], af[i], &bf[0][2]);
                mma_tf32(acc[i][2], af[i], &bf[1][0]);
                mma_tf32(acc[i][3], af[i], &bf[1][2]);
            }
        }
    }

    // ---- fused epilogue ----
    const int cRow = blockIdx.y * BM + wm * 64;
    const int cCol = blockIdx.x * BN + wn * 32;

    #pragma unroll
    for (int i = 0; i < 4; i++) {
        const int r0 = cRow + i * 16 + (l >> 2);
        #pragma unroll
        for (int j = 0; j < 4; j++) {
            const int col = cCol + j * 8 + (l & 3) * 2;
            const float2 bv = *reinterpret_cast<const float2*>(bias + col);
            float v0 = acc[i][j][0] + bv.x;
            float v1 = acc[i][j][1] + bv.y;
            float v2 = acc[i][j][2] + bv.x;
            float v3 = acc[i][j][3] + bv.y;
            if (ENC) {
                const float2 tv = *reinterpret_cast<const float2*>(thr + col);
                v0 = (v0 > tv.x) ? round_tf32(v0) : 0.f;
                v1 = (v1 > tv.y) ? round_tf32(v1) : 0.f;
                v2 = (v2 > tv.x) ? round_tf32(v2) : 0.f;
                v3 = (v3 > tv.y) ? round_tf32(v3) : 0.f;
            }
            const size_t o0 = (size_t)r0 * Nout + col;
            const size_t o1 = (size_t)(r0 + 8) * Nout + col;
            *reinterpret_cast<float2*>(C + o0) = make_float2(v0, v1);
            *reinterpret_cast<float2*>(C + o1) = make_float2(v2, v3);
        }
    }
}

// ------------------------------- launcher ----------------------------------
extern "C" void kernel_launch(void* const* d_in, const int* in_sizes, int n_in,
                              void* d_out, int out_size) {
    const float* x     = (const float*)d_in[0];   // [8192, 2048]
    const float* W_enc = (const float*)d_in[1];   // [2048, 16384]
    const float* b_enc = (const float*)d_in[2];   // [16384]
    const float* thr   = (const float*)d_in[3];   // [16384]
    const float* W_dec = (const float*)d_in[4];   // [16384, 2048]
    const float* b_dec = (const float*)d_in[5];   // [2048]

    const int Nrows = 8192, D = 2048, S = 16384;

    float* recon = (float*)d_out;                       // [8192, 2048]
    float* feats = (float*)d_out + (size_t)Nrows * D;   // [8192, 16384]

    float *wEncT, *wDecT, *xR, *biasPart, *biasEnc;
    cudaGetSymbolAddress((void**)&wEncT, g_WencT);
    cudaGetSymbolAddress((void**)&wDecT, g_WdecT);
    cudaGetSymbolAddress((void**)&xR, g_xR);
    cudaGetSymbolAddress((void**)&biasPart, g_biasPart);
    cudaGetSymbolAddress((void**)&biasEnc, g_biasEnc);

    cudaFuncSetAttribute(sae_gemm<true>,
                         cudaFuncAttributeMaxDynamicSharedMemorySize, SMEM_TOTAL);
    cudaFuncSetAttribute(sae_gemm<false>,
                         cudaFuncAttributeMaxDynamicSharedMemorySize, SMEM_TOTAL);

    // prep: tf32-rounded transposed weights, rounded x, effective encoder bias
    transpose_round_kernel<<<dim3(S / 32, D / 32), dim3(32, 8)>>>(W_enc, wEncT, D, S);
    transpose_round_kernel<<<dim3(D / 32, S / 32), dim3(32, 8)>>>(W_dec, wDecT, S, D);
    {
        size_t n4 = (size_t)Nrows * D / 4;
        round_kernel<<<(unsigned)((n4 + 255) / 256), 256>>>(x, xR, n4);
    }
    bias_part_kernel<<<dim3(S / 256, BC_SPLIT), 256>>>(W_enc, b_dec, biasPart, D, S);
    bias_reduce_kernel<<<S / 256, 256>>>(biasPart, b_enc, biasEnc, S);

    // encode: feats = round_tf32(JumpReLU(xR @ W_enc + bias_eff)) -> d_out
    sae_gemm<true><<<dim3(S / BN, Nrows / BM), NT, SMEM_TOTAL>>>(
        xR, wEncT, biasEnc, thr, feats, D, S);

    // decode: recon = feats @ W_dec + b_dec   (feats already tf32 values)
    sae_gemm<false><<<dim3(D / BN, Nrows / BM), NT, SMEM_TOTAL>>>(
        feats, wDecT, b_dec, nullptr, recon, S, D);
}